// round 9
// baseline (speedup 1.0000x reference)
#include <cuda_runtime.h>

// CRF forward log-partition. B=512, T=512, L=64.
// ONE WARP PER BATCH (32-thread blocks, grid=512). No __syncthreads anywhere.
// Linear-domain scan: v_{t+1}[n] = (sum_p E[n,p] v_t[p]) * exp(emit_t[n]) * scale
//  - Lane owns tags {lane, lane+32} and the FULL 64-prev dot product:
//    64 FFMA2/lane/step, E = exp(trans) in 128 f32 regs (pair-permuted layout).
//  - v exchange: STS.64 (own float2) -> __syncwarp -> 8x broadcast LDS.128.
//  - Renorm every 4 steps: 5-shfl max measured at slot 2 (off-chain), power-of-2
//    scale applied at next slot 0. acc2 incremented ONLY at application time so a
//    final measured-but-never-applied scale is discarded (R6 bug fix).
//  - Emissions: raw prefetch distance 4 (ring of 4 float2), ex2 convert 1 step
//    ahead -> MUFU never on the chain.

#define LOG2E 1.4426950408889634f
#define LN2   0.6931471805599453f

constexpr int L  = 64;
constexpr int TT = 512;

static __device__ __forceinline__ float ex2f(float x) {
    float r; asm("ex2.approx.ftz.f32 %0, %1;" : "=f"(r) : "f"(x)); return r;
}
static __device__ __forceinline__ float lg2f(float x) {
    float r; asm("lg2.approx.ftz.f32 %0, %1;" : "=f"(r) : "f"(x)); return r;
}
static __device__ __forceinline__ unsigned long long pk2(float lo, float hi) {
    unsigned long long r;
    asm("mov.b64 %0, {%1, %2};" : "=l"(r) : "f"(lo), "f"(hi)); return r;
}
static __device__ __forceinline__ void upk2(unsigned long long v, float& lo, float& hi) {
    asm("mov.b64 {%0, %1}, %2;" : "=f"(lo), "=f"(hi) : "l"(v));
}
static __device__ __forceinline__ unsigned long long ffma2(
    unsigned long long a, unsigned long long b, unsigned long long c) {
    unsigned long long d;
    asm("fma.rn.f32x2 %0, %1, %2, %3;" : "=l"(d) : "l"(a), "l"(b), "l"(c)); return d;
}
static __device__ __forceinline__ unsigned long long fadd2(
    unsigned long long a, unsigned long long b) {
    unsigned long long d;
    asm("add.rn.f32x2 %0, %1, %2;" : "=l"(d) : "l"(a), "l"(b)); return d;
}

__global__ __launch_bounds__(32) void crf_fwd(
    const float* __restrict__ emis,   // [B, T, L]
    const float* __restrict__ trans,  // [L, L]  trans[next*L + prev]
    float* __restrict__ out)          // [B]
{
    const int b    = blockIdx.x;
    const int lane = threadIdx.x;     // 0..31
    const int n0   = lane, n1 = lane + 32;
    const unsigned FULL = 0xffffffffu;

    // v buffers: 32 float2 pairs; pair p = (v[p], v[p+32])
    __shared__ __align__(16) float2 v_sh[2][32];

    // ---- E rows for both tags, pair-permuted: E0[p] = (e[n0][p], e[n0][p+32]) ----
    unsigned long long E0[32], E1[32];
    {
        float ex0[64], ex1[64];
        const float4* t0 = reinterpret_cast<const float4*>(trans + n0 * L);
        const float4* t1 = reinterpret_cast<const float4*>(trans + n1 * L);
        #pragma unroll
        for (int j = 0; j < 16; j++) {
            float4 a = t0[j];
            ex0[4 * j] = __expf(a.x); ex0[4 * j + 1] = __expf(a.y);
            ex0[4 * j + 2] = __expf(a.z); ex0[4 * j + 3] = __expf(a.w);
            float4 c = t1[j];
            ex1[4 * j] = __expf(c.x); ex1[4 * j + 1] = __expf(c.y);
            ex1[4 * j + 2] = __expf(c.z); ex1[4 * j + 3] = __expf(c.w);
        }
        #pragma unroll
        for (int p = 0; p < 32; p++) {
            E0[p] = pk2(ex0[p], ex0[p + 32]);
            E1[p] = pk2(ex1[p], ex1[p + 32]);
        }
    }
    const float Es0 = __expf(trans[(L - 1) * L + n0]);
    const float Es1 = __expf(trans[(L - 1) * L + n1]);

    // ---- init v0: delta(START=62) -> pair slot 30, hi half ----
    v_sh[0][lane] = make_float2(0.0f, (lane == 30) ? 1.0f : 0.0f);

    // ---- emission ring: raw distance 4, ex2 one step ahead ----
    const float* e0 = emis + (size_t)b * (TT * L) + n0;
    const float* e1 = e0 + 32;
    float2 raw[4];
    #pragma unroll
    for (int k = 0; k < 4; k++)
        raw[k] = make_float2(__ldg(e0 + k * L), __ldg(e1 + k * L));
    float2 fcur = make_float2(ex2f(raw[0].x * LOG2E), ex2f(raw[0].y * LOG2E));

    float scale = 1.0f;     // power-of-2 renorm factor (applied at s==0)
    int   pend  = 0;        // log2 of 'scale' (committed to acc2 only on apply)
    int   acc2  = 0;        // accumulated log2 of scales actually applied
    float v0 = 0.0f, v1 = 0.0f;
    int   buf = 0;
    __syncwarp();

    #pragma unroll 1
    for (int it = 0; it < TT / 4; ++it) {
        #pragma unroll
        for (int s = 0; s < 4; ++s) {
            const int t = it * 4 + s;

            float f0 = fcur.x, f1 = fcur.y;
            if (s == 0) { f0 *= scale; f1 *= scale; acc2 += pend; }

            // ---- full 64-prev dot for both tags: 8 broadcast LDS.128 ----
            const ulonglong2* vv = reinterpret_cast<const ulonglong2*>(v_sh[buf]);
            unsigned long long c0 = 0ull, c1 = 0ull, c2 = 0ull, c3 = 0ull;
            unsigned long long d0 = 0ull, d1 = 0ull, d2 = 0ull, d3 = 0ull;
            #pragma unroll
            for (int k = 0; k < 16; k += 2) {
                ulonglong2 qa = vv[k];       // pairs 2k, 2k+1
                ulonglong2 qb = vv[k + 1];   // pairs 2k+2, 2k+3
                c0 = ffma2(qa.x, E0[2 * k],     c0);
                c1 = ffma2(qa.y, E0[2 * k + 1], c1);
                c2 = ffma2(qb.x, E0[2 * k + 2], c2);
                c3 = ffma2(qb.y, E0[2 * k + 3], c3);
                d0 = ffma2(qa.x, E1[2 * k],     d0);
                d1 = ffma2(qa.y, E1[2 * k + 1], d1);
                d2 = ffma2(qb.x, E1[2 * k + 2], d2);
                d3 = ffma2(qb.y, E1[2 * k + 3], d3);
            }
            float s0, s1;
            { float lo, hi; upk2(fadd2(fadd2(c0, c1), fadd2(c2, c3)), lo, hi); s0 = lo + hi; }
            { float lo, hi; upk2(fadd2(fadd2(d0, d1), fadd2(d2, d3)), lo, hi); s1 = lo + hi; }

            v0 = s0 * f0;
            v1 = s1 * f1;

            v_sh[buf ^ 1][lane] = make_float2(v0, v1);

            if (s == 2) {
                // measure max; 5-shfl chain has ~2 steps to complete (off-chain)
                float wm = fmaxf(v0, v1);
                #pragma unroll
                for (int o = 16; o >= 1; o >>= 1)
                    wm = fmaxf(wm, __shfl_xor_sync(FULL, wm, o));
                int ei = (int)((__float_as_uint(wm) >> 23) & 0xff);
                scale = __uint_as_float((unsigned)(253 - ei) << 23); // 2^(126-ei)
                pend  = ei - 126;
            }

            // prefetch emissions t+4 into slot s; convert slot s+1 for next step
            {
                int tp = (t + 4 < TT) ? t + 4 : TT - 1;
                raw[s] = make_float2(__ldg(e0 + (size_t)tp * L),
                                     __ldg(e1 + (size_t)tp * L));
                float2 rn = raw[(s + 1) & 3];
                fcur = make_float2(ex2f(rn.x * LOG2E), ex2f(rn.y * LOG2E));
            }

            __syncwarp();
            buf ^= 1;
        }
    }

    // ---- terminal: log(sum_n v[n]*exp(trans[STOP][n])) + acc2*ln2 ----
    // (pending scale from the last s==2 measurement was never applied -> ignored)
    float term = fmaf(v1, Es1, v0 * Es0);
    #pragma unroll
    for (int o = 16; o >= 1; o >>= 1) term += __shfl_xor_sync(FULL, term, o);
    if (lane == 0) out[b] = (lg2f(term) + (float)acc2) * LN2;
}

extern "C" void kernel_launch(void* const* d_in, const int* in_sizes, int n_in,
                              void* d_out, int out_size) {
    const float* emis  = (const float*)d_in[0];   // [B, T, L] float32
    const float* trans = (const float*)d_in[1];   // [L, L] float32
    float* out = (float*)d_out;                   // [B] float32
    int B = in_sizes[0] / (TT * L);
    crf_fwd<<<B, 32>>>(emis, trans, out);
}

// round 10
// speedup vs baseline: 1.5918x; 1.5918x over previous
#include <cuda_runtime.h>

// CRF forward log-partition. B=512, T=512, L=64.
// TIME-SPLIT: Z = w^T v;  v = M_255..M_0 delta (forward),  w = M_256^T..M_511^T Estop
// (backward, recurrence w <- E^T (w o f_t) == same structure with E transposed,
// emissions reversed and pre-multiplied, Estop folded into the init).
// Block = 256 threads = 1 batch: warps 0-3 forward half, warps 4-7 backward half.
// Each half is the proven R3 step: thread (g,q) owns tags {g,g+32} x prev-quarter q,
// packed f32x2 FMA, padded conflict-free LDS, renorm every 4 steps (applied at s==0,
// acc2 updated at apply time -> final pending scale naturally discarded).
// __launch_bounds__(256,4): 4 blocks/SM (single wave at grid=512) needs <=62 regs.

#define LOG2E 1.4426950408889634f
#define LN2   0.6931471805599453f

constexpr int L    = 64;
constexpr int TT   = 512;
constexpr int HALF = 256;
constexpr int VPAD = 20;   // padded quarter stride (floats) -> disjoint-bank broadcasts

static __device__ __forceinline__ float ex2f(float x) {
    float r; asm("ex2.approx.ftz.f32 %0, %1;" : "=f"(r) : "f"(x)); return r;
}
static __device__ __forceinline__ float lg2f(float x) {
    float r; asm("lg2.approx.ftz.f32 %0, %1;" : "=f"(r) : "f"(x)); return r;
}
static __device__ __forceinline__ unsigned long long pk2(float lo, float hi) {
    unsigned long long r;
    asm("mov.b64 %0, {%1, %2};" : "=l"(r) : "f"(lo), "f"(hi)); return r;
}
static __device__ __forceinline__ void upk2(unsigned long long v, float& lo, float& hi) {
    asm("mov.b64 {%0, %1}, %2;" : "=f"(lo), "=f"(hi) : "l"(v));
}
static __device__ __forceinline__ unsigned long long ffma2(
    unsigned long long a, unsigned long long b, unsigned long long c) {
    unsigned long long d;
    asm("fma.rn.f32x2 %0, %1, %2, %3;" : "=l"(d) : "l"(a), "l"(b), "l"(c)); return d;
}
static __device__ __forceinline__ unsigned long long fadd2(
    unsigned long long a, unsigned long long b) {
    unsigned long long d;
    asm("add.rn.f32x2 %0, %1, %2;" : "=l"(d) : "l"(a), "l"(b)); return d;
}

__global__ __launch_bounds__(256, 4) void crf_fwd(
    const float* __restrict__ emis,   // [B, T, L]
    const float* __restrict__ trans,  // [L, L]  trans[next*L + prev]
    float* __restrict__ out)          // [B]
{
    const int b    = blockIdx.x;
    const int tid  = threadIdx.x;
    const int wg   = tid >> 7;       // 0 = forward, 1 = backward
    const int wtid = tid & 127;
    const int g    = wtid >> 2;      // 0..31 -> tags g, g+32
    const int q    = wtid & 3;       // prev-quarter
    const int wloc = wtid >> 5;      // warp within group 0..3
    const unsigned FULL = 0xffffffffu;

    __shared__ __align__(16) float v_sh[2][2][4 * VPAD];
    __shared__ __align__(16) float red_sh[2][4];
    __shared__ __align__(16) float fin[2][64];
    __shared__ int acc_sh[2];

    const int n0 = g, n1 = g + 32;

    // ---- E slice (2 tags x 16 prevs) into packed pairs ----
    // fw: rows of exp(trans);  bw: COLUMNS (transposed), prev index = source tag n.
    unsigned long long E0[8], E1[8];
    if (wg == 0) {
        const float4* r0 = reinterpret_cast<const float4*>(trans + n0 * L + q * 16);
        const float4* r1 = reinterpret_cast<const float4*>(trans + n1 * L + q * 16);
        #pragma unroll
        for (int j = 0; j < 4; j++) {
            float4 a = r0[j];
            E0[2 * j]     = pk2(__expf(a.x), __expf(a.y));
            E0[2 * j + 1] = pk2(__expf(a.z), __expf(a.w));
            float4 c = r1[j];
            E1[2 * j]     = pk2(__expf(c.x), __expf(c.y));
            E1[2 * j + 1] = pk2(__expf(c.z), __expf(c.w));
        }
    } else {
        #pragma unroll
        for (int j = 0; j < 8; j++) {
            int r = q * 16 + 2 * j;
            E0[j] = pk2(__expf(trans[(r)     * L + n0]),
                        __expf(trans[(r + 1) * L + n0]));
            E1[j] = pk2(__expf(trans[(r)     * L + n1]),
                        __expf(trans[(r + 1) * L + n1]));
        }
    }

    // ---- init shared state ----
    if (wtid < L) {
        int m = (wtid >> 4) * VPAD + (wtid & 15);
        if (wg == 0) {
            v_sh[0][0][m] = (wtid == L - 2) ? 1.0f : 0.0f;   // delta(START)
        } else {
            // w~ init = exp(trans[STOP][n]) * exp(emit[511][n])
            float es = __expf(trans[(L - 1) * L + wtid]);
            float fe = ex2f(__ldg(emis + (size_t)b * (TT * L) + 511 * L + wtid) * LOG2E);
            v_sh[1][0][m] = es * fe;
        }
    }
    if (wtid < 4) red_sh[wg][wtid] = 1.0f;

    // ---- emission stream: fw t=0..255 ascending; bw t=510 descending (masked at j>254 -> f=1) ----
    const float* ebase = emis + (size_t)b * (TT * L) + (wg ? 510 * L : 0) + n0;
    const int dir = wg ? -L : L;
    float eA0 = ex2f(__ldg(ebase)            * LOG2E);
    float eA1 = ex2f(__ldg(ebase + 32)       * LOG2E);
    float eB0 = ex2f(__ldg(ebase + dir)      * LOG2E);
    float eB1 = ex2f(__ldg(ebase + dir + 32) * LOG2E);

    float* vbase = &v_sh[wg][0][0];
    int   acc2 = 0;
    float v0 = 0.0f, v1 = 0.0f;
    int   buf = 0;
    __syncthreads();

    #pragma unroll 1
    for (int it = 0; it < HALF / 4; ++it) {
        #pragma unroll
        for (int s = 0; s < 4; ++s) {
            const int j = it * 4 + s;

            float f0 = eA0, f1 = eA1;
            if (s == 0) {
                // apply renorm measured at previous slot 3 (acc2 updated on APPLY)
                float4 rv = *reinterpret_cast<const float4*>(red_sh[wg]);
                float m = fmaxf(fmaxf(rv.x, rv.y), fmaxf(rv.z, rv.w));
                int ei = (int)((__float_as_uint(m) >> 23) & 0xff);
                float scale = __uint_as_float((unsigned)(253 - ei) << 23); // 2^(126-ei)
                acc2 += ei - 126;
                f0 *= scale; f1 *= scale;
            }

            // ---- matvec quarter: 2 tags x 16 prevs, packed f32x2 ----
            const ulonglong2* vv =
                reinterpret_cast<const ulonglong2*>(vbase + buf * (4 * VPAD) + q * VPAD);
            ulonglong2 p0 = vv[0], p1 = vv[1], p2 = vv[2], p3 = vv[3];

            unsigned long long c00 = ffma2(p0.x, E0[0], 0ull);
            unsigned long long c01 = ffma2(p0.y, E0[1], 0ull);
            unsigned long long c10 = ffma2(p0.x, E1[0], 0ull);
            unsigned long long c11 = ffma2(p0.y, E1[1], 0ull);
            c00 = ffma2(p1.x, E0[2], c00);  c01 = ffma2(p1.y, E0[3], c01);
            c10 = ffma2(p1.x, E1[2], c10);  c11 = ffma2(p1.y, E1[3], c11);
            c00 = ffma2(p2.x, E0[4], c00);  c01 = ffma2(p2.y, E0[5], c01);
            c10 = ffma2(p2.x, E1[4], c10);  c11 = ffma2(p2.y, E1[5], c11);
            c00 = ffma2(p3.x, E0[6], c00);  c01 = ffma2(p3.y, E0[7], c01);
            c10 = ffma2(p3.x, E1[6], c10);  c11 = ffma2(p3.y, E1[7], c11);

            float s0, s1;
            { float lo, hi; upk2(fadd2(c00, c01), lo, hi); s0 = lo + hi; }
            { float lo, hi; upk2(fadd2(c10, c11), lo, hi); s1 = lo + hi; }

            // combine across the 4 prev-quarters (lanes q = tid&3)
            s0 += __shfl_xor_sync(FULL, s0, 1);
            s1 += __shfl_xor_sync(FULL, s1, 1);
            s0 += __shfl_xor_sync(FULL, s0, 2);
            s1 += __shfl_xor_sync(FULL, s1, 2);

            v0 = s0 * f0;
            v1 = s1 * f1;

            if (q == 0) {
                float* dst = vbase + (buf ^ 1) * (4 * VPAD);
                dst[(n0 >> 4) * VPAD + (n0 & 15)] = v0;
                dst[(n1 >> 4) * VPAD + (n1 & 15)] = v1;
            }

            if (s == 3) {
                float wm = fmaxf(v0, v1);
                #pragma unroll
                for (int o = 16; o >= 1; o >>= 1)
                    wm = fmaxf(wm, __shfl_xor_sync(FULL, wm, o));
                if ((wtid & 31) == 0) red_sh[wg][wloc] = wm;
            }

            // prefetch emissions j+2 (ex2 off the critical path); bw masks j>254 -> f=1
            {
                int jp = j + 2;
                float r0 = __ldg(ebase + jp * dir);
                float r1 = __ldg(ebase + jp * dir + 32);
                if (wg && jp > 254) { r0 = 0.0f; r1 = 0.0f; }
                eA0 = eB0; eA1 = eB1;
                eB0 = ex2f(r0 * LOG2E);
                eB1 = ex2f(r1 * LOG2E);
            }

            __syncthreads();
            buf ^= 1;
        }
    }

    // ---- combine: Z = sum_n v[n] * w[n], scales add ----
    if (q == 0) { fin[wg][n0] = v0; fin[wg][n1] = v1; }
    if (wtid == 0) acc_sh[wg] = acc2;
    __syncthreads();
    if (tid < 32) {
        float p = fin[0][tid] * fin[1][tid] + fin[0][tid + 32] * fin[1][tid + 32];
        #pragma unroll
        for (int o = 16; o >= 1; o >>= 1) p += __shfl_xor_sync(FULL, p, o);
        if (tid == 0)
            out[b] = (lg2f(p) + (float)(acc_sh[0] + acc_sh[1])) * LN2;
    }
}

extern "C" void kernel_launch(void* const* d_in, const int* in_sizes, int n_in,
                              void* d_out, int out_size) {
    const float* emis  = (const float*)d_in[0];   // [B, T, L] float32
    const float* trans = (const float*)d_in[1];   // [L, L] float32
    float* out = (float*)d_out;                   // [B] float32
    int B = in_sizes[0] / (TT * L);
    crf_fwd<<<B, 256>>>(emis, trans, out);
}

// round 13
// speedup vs baseline: 2.2056x; 1.3856x over previous
#include <cuda_runtime.h>

// CRF forward log-partition. B=512, T=512, L=64.
// TIME-SPLIT (fwd x bwd halves meeting at T/2) + ONE TAG PER THREAD.
// Block = 128 threads = 1 batch: threads 0-63 forward, 64-127 backward.
// Each thread owns one tag and computes the FULL 64-prev dot product:
//   32 FFMA2 (4 chains depth 8), v exchange = 1 STS.32 + 8 broadcast LDS.128,
//   NO combine shuffles. E (row for fwd / column for bwd) = 64 f32 regs.
// Renorm every 4 steps: per-warp max at s==3 -> red_sh, applied at next s==0
// (acc2 updated at APPLY time; final pending scale correctly discarded).
// Emissions: 1 float/thread/step, prefetch distance 2, ex2 off the chain.
// Combine: Z = sum_n v_fwd[n] * w_bwd[n], scales add in log2.

#define LOG2E 1.4426950408889634f
#define LN2   0.6931471805599453f

constexpr int L    = 64;
constexpr int TT   = 512;
constexpr int HALF = 256;

static __device__ __forceinline__ float ex2f(float x) {
    float r; asm("ex2.approx.ftz.f32 %0, %1;" : "=f"(r) : "f"(x)); return r;
}
static __device__ __forceinline__ float lg2f(float x) {
    float r; asm("lg2.approx.ftz.f32 %0, %1;" : "=f"(r) : "f"(x)); return r;
}
static __device__ __forceinline__ unsigned long long pk2(float lo, float hi) {
    unsigned long long r;
    asm("mov.b64 %0, {%1, %2};" : "=l"(r) : "f"(lo), "f"(hi)); return r;
}
static __device__ __forceinline__ void upk2(unsigned long long v, float& lo, float& hi) {
    asm("mov.b64 {%0, %1}, %2;" : "=f"(lo), "=f"(hi) : "l"(v));
}
static __device__ __forceinline__ unsigned long long ffma2(
    unsigned long long a, unsigned long long b, unsigned long long c) {
    unsigned long long d;
    asm("fma.rn.f32x2 %0, %1, %2, %3;" : "=l"(d) : "l"(a), "l"(b), "l"(c)); return d;
}
static __device__ __forceinline__ unsigned long long fadd2(
    unsigned long long a, unsigned long long b) {
    unsigned long long d;
    asm("add.rn.f32x2 %0, %1, %2;" : "=l"(d) : "l"(a), "l"(b)); return d;
}

__global__ __launch_bounds__(128, 4) void crf_fwd(
    const float* __restrict__ emis,   // [B, T, L]
    const float* __restrict__ trans,  // [L, L]  trans[next*L + prev]
    float* __restrict__ out)          // [B]
{
    const int b   = blockIdx.x;
    const int tid = threadIdx.x;
    const int dir = tid >> 6;        // 0 = forward, 1 = backward
    const int n   = tid & 63;        // tag
    const int wh  = (tid >> 5) & 1;  // warp within direction (0/1)
    const unsigned FULL = 0xffffffffu;

    __shared__ __align__(16) float v_sh[2][2][L];   // [dir][buf][tag]
    __shared__ __align__(16) float red_sh[2][2];    // [dir][warp-half]
    __shared__ __align__(16) float fin[2][L];
    __shared__ int acc_sh[2];

    // ---- E vector for this tag: fwd = row n of exp(trans); bwd = column n ----
    unsigned long long E[32];
    if (dir == 0) {
        const float4* tr = reinterpret_cast<const float4*>(trans + n * L);
        #pragma unroll
        for (int j = 0; j < 16; j++) {
            float4 a = tr[j];
            E[2 * j]     = pk2(__expf(a.x), __expf(a.y));
            E[2 * j + 1] = pk2(__expf(a.z), __expf(a.w));
        }
    } else {
        #pragma unroll
        for (int j = 0; j < 32; j++) {
            E[j] = pk2(__expf(trans[(2 * j)     * L + n]),
                       __expf(trans[(2 * j + 1) * L + n]));
        }
    }

    // ---- init state ----
    if (dir == 0) {
        v_sh[0][0][n] = (n == L - 2) ? 1.0f : 0.0f;                 // delta(START)
    } else {
        // w init = exp(trans[STOP][n]) * exp(emit[511][n])
        float es = __expf(trans[(L - 1) * L + n]);
        float fe = ex2f(__ldg(emis + (size_t)b * (TT * L) + 511 * L + n) * LOG2E);
        v_sh[1][0][n] = es * fe;
    }
    if ((tid & 31) == 0) red_sh[dir][wh] = 1.0f;

    // ---- emission stream: fwd t=0.. ascending; bwd t=510.. descending ----
    // bwd round j uses f = exp(emit[510-j]); j>254 masked to f=1 (handled via r=0).
    const int dstep = dir ? -L : L;
    const float* eptr = emis + (size_t)b * (TT * L) + (dir ? 510 * L : 0) + n;
    float eA = ex2f(__ldg(eptr) * LOG2E);
    float eB = ex2f(__ldg(eptr + dstep) * LOG2E);
    const float* pf = eptr + 2 * dstep;   // prefetch pointer (round j+2)

    int   acc2 = 0;
    float v    = 0.0f;
    int   buf  = 0;
    __syncthreads();

    #pragma unroll 1
    for (int it = 0; it < HALF / 4; ++it) {
        #pragma unroll
        for (int s = 0; s < 4; ++s) {
            const int j = it * 4 + s;

            float f = eA;
            if (s == 0) {
                // apply renorm measured at previous slot 3 (acc2 updated on APPLY)
                float2 rv = *reinterpret_cast<const float2*>(red_sh[dir]);
                float m = fmaxf(rv.x, rv.y);
                int ei = (int)((__float_as_uint(m) >> 23) & 0xff);
                float scale = __uint_as_float((unsigned)(253 - ei) << 23); // 2^(126-ei)
                acc2 += ei - 126;
                f *= scale;
            }

            // ---- full 64-prev dot: 8 broadcast LDS.128, 32 FFMA2 (4 chains x8) ----
            const ulonglong2* vv =
                reinterpret_cast<const ulonglong2*>(&v_sh[dir][buf][0]);
            unsigned long long c0, c1, c2, c3;
            {
                ulonglong2 qa = vv[0], qb = vv[1];
                c0 = ffma2(qa.x, E[0], 0ull);
                c1 = ffma2(qa.y, E[1], 0ull);
                c2 = ffma2(qb.x, E[2], 0ull);
                c3 = ffma2(qb.y, E[3], 0ull);
            }
            #pragma unroll
            for (int k = 1; k < 8; k++) {
                ulonglong2 qa = vv[2 * k], qb = vv[2 * k + 1];
                c0 = ffma2(qa.x, E[4 * k],     c0);
                c1 = ffma2(qa.y, E[4 * k + 1], c1);
                c2 = ffma2(qb.x, E[4 * k + 2], c2);
                c3 = ffma2(qb.y, E[4 * k + 3], c3);
            }
            float s0;
            { float lo, hi; upk2(fadd2(fadd2(c0, c1), fadd2(c2, c3)), lo, hi); s0 = lo + hi; }

            v = s0 * f;
            v_sh[dir][buf ^ 1][n] = v;

            if (s == 3) {
                float wm = v;
                #pragma unroll
                for (int o = 16; o >= 1; o >>= 1)
                    wm = fmaxf(wm, __shfl_xor_sync(FULL, wm, o));
                if ((tid & 31) == 0) red_sh[dir][wh] = wm;
            }

            // prefetch emission for round j+2 (bwd: mask rounds > 254 -> f=1)
            {
                float r = __ldg(pf);
                pf += dstep;
                if (dir && (j + 2 > 254)) r = 0.0f;
                eA = eB;
                eB = ex2f(r * LOG2E);
            }

            __syncthreads();
            buf ^= 1;
        }
    }

    // ---- combine: Z = sum_n v[n] * w[n]; scales add in log2 ----
    fin[dir][n] = v;
    if (tid == 0 || tid == 64) acc_sh[dir] = acc2;
    __syncthreads();
    if (tid < 32) {
        float p = fin[0][tid] * fin[1][tid] + fin[0][tid + 32] * fin[1][tid + 32];
        #pragma unroll
        for (int o = 16; o >= 1; o >>= 1) p += __shfl_xor_sync(FULL, p, o);
        if (tid == 0)
            out[b] = (lg2f(p) + (float)(acc_sh[0] + acc_sh[1])) * LN2;
    }
}

extern "C" void kernel_launch(void* const* d_in, const int* in_sizes, int n_in,
                              void* d_out, int out_size) {
    const float* emis  = (const float*)d_in[0];   // [B, T, L] float32
    const float* trans = (const float*)d_in[1];   // [L, L] float32
    float* out = (float*)d_out;                   // [B] float32
    int B = in_sizes[0] / (TT * L);
    crf_fwd<<<B, 128>>>(emis, trans, out);
}

// round 14
// speedup vs baseline: 3.0766x; 1.3949x over previous
#include <cuda_runtime.h>

// CRF forward log-partition. B=512, T=512, L=64.
// TIME-SPLIT + WARP-AUTONOMOUS: block = 128 thr = 2 batches;
// warp w: batch blockIdx*2+(w>>1), direction w&1 (0=fwd, 1=bwd).
// Each warp runs its 256-round half completely independently:
//   lane owns tags {lane, lane+32}, FULL 64-prev dot (64 FFMA2, pair-packed),
//   v exchange = STS.64 + __syncwarp + 16 broadcast LDS.128. NO __syncthreads
//   in the main loop. Renorm every 4 rounds: warp shfl-max at s==2 (off-chain),
//   power-of-2 scale applied at next s==0, acc2 committed at APPLY time.
// Combine: Z = sum_n v_fwd[n] * w_bwd[n]; log2-scales add.

#define LOG2E 1.4426950408889634f
#define LN2   0.6931471805599453f

constexpr int L    = 64;
constexpr int TT   = 512;
constexpr int HALF = 256;

static __device__ __forceinline__ float ex2f(float x) {
    float r; asm("ex2.approx.ftz.f32 %0, %1;" : "=f"(r) : "f"(x)); return r;
}
static __device__ __forceinline__ float lg2f(float x) {
    float r; asm("lg2.approx.ftz.f32 %0, %1;" : "=f"(r) : "f"(x)); return r;
}
static __device__ __forceinline__ unsigned long long pk2(float lo, float hi) {
    unsigned long long r;
    asm("mov.b64 %0, {%1, %2};" : "=l"(r) : "f"(lo), "f"(hi)); return r;
}
static __device__ __forceinline__ void upk2(unsigned long long v, float& lo, float& hi) {
    asm("mov.b64 {%0, %1}, %2;" : "=f"(lo), "=f"(hi) : "l"(v));
}
static __device__ __forceinline__ unsigned long long ffma2(
    unsigned long long a, unsigned long long b, unsigned long long c) {
    unsigned long long d;
    asm("fma.rn.f32x2 %0, %1, %2, %3;" : "=l"(d) : "l"(a), "l"(b), "l"(c)); return d;
}
static __device__ __forceinline__ unsigned long long fadd2(
    unsigned long long a, unsigned long long b) {
    unsigned long long d;
    asm("add.rn.f32x2 %0, %1, %2;" : "=l"(d) : "l"(a), "l"(b)); return d;
}

__global__ __launch_bounds__(128, 2) void crf_fwd(
    const float* __restrict__ emis,   // [B, T, L]
    const float* __restrict__ trans,  // [L, L]  trans[next*L + prev]
    float* __restrict__ out)          // [B]
{
    const int tid  = threadIdx.x;
    const int w    = tid >> 5;           // warp 0..3
    const int lane = tid & 31;
    const int dir  = w & 1;              // 0 = forward, 1 = backward
    const int b    = blockIdx.x * 2 + (w >> 1);
    const int n0   = lane, n1 = lane + 32;
    const unsigned FULL = 0xffffffffu;

    // per-warp double-buffered v: pair p = (v[p], v[p+32])
    __shared__ __align__(16) float2 v_sh[4][2][32];
    __shared__ __align__(16) float2 fin[4][32];
    __shared__ int acc_sh[4];

    // ---- E for both tags, pair-packed: fwd rows / bwd columns of exp(trans) ----
    unsigned long long E0[32], E1[32];
    if (dir == 0) {
        float ex0[64], ex1[64];
        const float4* t0 = reinterpret_cast<const float4*>(trans + n0 * L);
        const float4* t1 = reinterpret_cast<const float4*>(trans + n1 * L);
        #pragma unroll
        for (int j = 0; j < 16; j++) {
            float4 a = t0[j];
            ex0[4 * j] = __expf(a.x); ex0[4 * j + 1] = __expf(a.y);
            ex0[4 * j + 2] = __expf(a.z); ex0[4 * j + 3] = __expf(a.w);
            float4 c = t1[j];
            ex1[4 * j] = __expf(c.x); ex1[4 * j + 1] = __expf(c.y);
            ex1[4 * j + 2] = __expf(c.z); ex1[4 * j + 3] = __expf(c.w);
        }
        #pragma unroll
        for (int p = 0; p < 32; p++) {
            E0[p] = pk2(ex0[p], ex0[p + 32]);
            E1[p] = pk2(ex1[p], ex1[p + 32]);
        }
    } else {
        #pragma unroll
        for (int p = 0; p < 32; p++) {
            E0[p] = pk2(__expf(trans[p * L + n0]), __expf(trans[(p + 32) * L + n0]));
            E1[p] = pk2(__expf(trans[p * L + n1]), __expf(trans[(p + 32) * L + n1]));
        }
    }

    // ---- init state + emission stream ----
    const int dstep = dir ? -L : L;
    const float* ebase = emis + (size_t)b * (TT * L) + (dir ? 510 * L : 0) + lane;
    if (dir == 0) {
        v_sh[w][0][lane] = make_float2(0.0f, (lane == 30) ? 1.0f : 0.0f); // delta(START=62)
    } else {
        // w init = exp(trans[STOP][n]) * exp(emit[511][n])
        float es0 = __expf(trans[(L - 1) * L + n0]);
        float es1 = __expf(trans[(L - 1) * L + n1]);
        const float* e511 = emis + (size_t)b * (TT * L) + 511 * L + lane;
        float fe0 = ex2f(__ldg(e511)      * LOG2E);
        float fe1 = ex2f(__ldg(e511 + 32) * LOG2E);
        v_sh[w][0][lane] = make_float2(es0 * fe0, es1 * fe1);
    }

    // converted f for rounds j and j+1 (prefetch distance 2)
    float2 eA = make_float2(ex2f(__ldg(ebase)      * LOG2E),
                            ex2f(__ldg(ebase + 32) * LOG2E));
    float2 eB = make_float2(ex2f(__ldg(ebase + dstep)      * LOG2E),
                            ex2f(__ldg(ebase + dstep + 32) * LOG2E));
    const float* pf = ebase + 2 * dstep;

    float scale = 1.0f;
    int   pend  = 0;
    int   acc2  = 0;
    float v0 = 0.0f, v1 = 0.0f;
    int   buf = 0;
    __syncwarp();

    #pragma unroll 1
    for (int it = 0; it < HALF / 4; ++it) {
        #pragma unroll
        for (int s = 0; s < 4; ++s) {
            const int j = it * 4 + s;

            float f0 = eA.x, f1 = eA.y;
            if (s == 0) { f0 *= scale; f1 *= scale; acc2 += pend; }

            // ---- full 64-prev dot for both tags: 16 broadcast LDS.128, 64 FFMA2 ----
            const ulonglong2* vv = reinterpret_cast<const ulonglong2*>(v_sh[w][buf]);
            unsigned long long c0 = 0ull, c1 = 0ull, c2 = 0ull, c3 = 0ull;
            unsigned long long d0 = 0ull, d1 = 0ull, d2 = 0ull, d3 = 0ull;
            #pragma unroll
            for (int k = 0; k < 16; k += 2) {
                ulonglong2 qa = vv[k];       // pairs 2k, 2k+1
                ulonglong2 qb = vv[k + 1];   // pairs 2k+2, 2k+3
                c0 = ffma2(qa.x, E0[2 * k],     c0);
                c1 = ffma2(qa.y, E0[2 * k + 1], c1);
                c2 = ffma2(qb.x, E0[2 * k + 2], c2);
                c3 = ffma2(qb.y, E0[2 * k + 3], c3);
                d0 = ffma2(qa.x, E1[2 * k],     d0);
                d1 = ffma2(qa.y, E1[2 * k + 1], d1);
                d2 = ffma2(qb.x, E1[2 * k + 2], d2);
                d3 = ffma2(qb.y, E1[2 * k + 3], d3);
            }
            float s0, s1;
            { float lo, hi; upk2(fadd2(fadd2(c0, c1), fadd2(c2, c3)), lo, hi); s0 = lo + hi; }
            { float lo, hi; upk2(fadd2(fadd2(d0, d1), fadd2(d2, d3)), lo, hi); s1 = lo + hi; }

            v0 = s0 * f0;
            v1 = s1 * f1;

            v_sh[w][buf ^ 1][lane] = make_float2(v0, v1);

            if (s == 2) {
                // measure max; applied at next s==0 (acc2 committed on APPLY,
                // final measured-but-unapplied scale correctly discarded)
                float wm = fmaxf(v0, v1);
                #pragma unroll
                for (int o = 16; o >= 1; o >>= 1)
                    wm = fmaxf(wm, __shfl_xor_sync(FULL, wm, o));
                int ei = (int)((__float_as_uint(wm) >> 23) & 0xff);
                scale = __uint_as_float((unsigned)(253 - ei) << 23); // 2^(126-ei)
                pend  = ei - 126;
            }

            // prefetch f for round j+2 (bwd masks rounds > 254 -> f = 1)
            {
                float r0 = __ldg(pf);
                float r1 = __ldg(pf + 32);
                pf += dstep;
                if (dir && (j + 2 > 254)) { r0 = 0.0f; r1 = 0.0f; }
                eA = eB;
                eB = make_float2(ex2f(r0 * LOG2E), ex2f(r1 * LOG2E));
            }

            __syncwarp();
            buf ^= 1;
        }
    }

    // ---- combine per batch: Z = sum_n v[n]*w[n]; log2-scales add ----
    fin[w][lane] = make_float2(v0, v1);
    if (lane == 0) acc_sh[w] = acc2;
    __syncthreads();
    if ((w & 1) == 0) {                     // warps 0 and 2
        float2 a = fin[w][lane];
        float2 c = fin[w + 1][lane];
        float p = a.x * c.x + a.y * c.y;
        #pragma unroll
        for (int o = 16; o >= 1; o >>= 1) p += __shfl_xor_sync(FULL, p, o);
        if (lane == 0)
            out[b] = (lg2f(p) + (float)(acc_sh[w] + acc_sh[w + 1])) * LN2;
    }
}

extern "C" void kernel_launch(void* const* d_in, const int* in_sizes, int n_in,
                              void* d_out, int out_size) {
    const float* emis  = (const float*)d_in[0];   // [B, T, L] float32
    const float* trans = (const float*)d_in[1];   // [L, L] float32
    float* out = (float*)d_out;                   // [B] float32
    int B = in_sizes[0] / (TT * L);
    crf_fwd<<<B / 2, 128>>>(emis, trans, out);
}